// round 15
// baseline (speedup 1.0000x reference)
#include <cuda_runtime.h>
#include <cuda_fp16.h>
#include <cstdint>

#define N_NODES 2048
#define N_EDGES 8192
#define EDGE_DIM 10
#define EH 32
#define HID 160
#define NW (HID*HID)                 // 25600
#define COL_B2 (EH*HID)              // 5120
#define COL_ROOT (EH*HID + HID)      // 5280
#define NCOLS (EH*HID + HID + HID)   // 5440
#define NROWS_PAD 5504               // NCOLS padded to 128 multiple

// fp16 k-permutation within 16-blocks: thread tig reads orig k
// {2t,2t+1,8+2t,8+2t+1} as 4 contiguous halves at pos 4t..4t+3.
__host__ __device__ __forceinline__ int kp16(int k) {
    return (k & ~15) | (((k & 7) >> 1) << 2) | ((k & 8) >> 2) | (k & 1);
}

// ---------------- device scratch ----------------
__device__ __half g_At[2][NROWS_PAD * HID];     // W^T [n][k], kp16 cols, fp16
__device__ __half g_x[2][N_NODES * HID];        // features, kp16 cols, fp16
__device__ __half g_Yh[(size_t)N_NODES * COL_ROOT]; // Y msg+b2 cols, fp16
__device__ float  g_Yroot[N_NODES * HID];       // Y root cols, fp32
__device__ float  g_h[2][N_EDGES * EH];
__device__ float  g_accum[N_NODES * HID];
__device__ int    g_cnt[N_NODES];
__device__ int    g_dst[N_EDGES];
__device__ int    g_csr_off[N_NODES + 1];
__device__ int    g_csr_edge[N_EDGES];

// =====================================================================
// Preprocessing (one block)
// =====================================================================
__global__ __launch_bounds__(1024) void prep_kernel(const void* __restrict__ eiraw) {
    __shared__ int s_flag;
    __shared__ int s_cs[N_NODES];
    __shared__ int s_cd[N_NODES];
    __shared__ int s_a[N_NODES];
    __shared__ int s_b[N_NODES];
    int t = threadIdx.x;

    for (int i = t; i < N_NODES; i += 1024) { s_cs[i] = 0; s_cd[i] = 0; }
    if (t == 0) s_flag = 0;
    __syncthreads();

    const int* raw = (const int*)eiraw;
    int f = 0;
    for (int i = t; i < N_EDGES; i += 1024)
        if (raw[2 * i + 1] != 0) f = 1;
    if (f) atomicOr(&s_flag, 1);
    __syncthreads();
    int flag = s_flag;

    int es[8], ed[8];
    #pragma unroll
    for (int j = 0; j < 8; j++) {
        int e = t + 1024 * j;
        if (flag) {
            es[j] = raw[e]; ed[j] = raw[N_EDGES + e];
        } else {
            const long long* p = (const long long*)eiraw;
            es[j] = (int)p[e]; ed[j] = (int)p[N_EDGES + e];
        }
        atomicAdd(&s_cs[es[j]], 1);
        atomicAdd(&s_cd[ed[j]], 1);
        g_dst[e] = ed[j];
    }
    __syncthreads();

    for (int i = t; i < N_NODES; i += 1024) { g_cnt[i] = s_cd[i]; s_a[i] = s_cs[i]; }
    __syncthreads();

    int* pa = s_a; int* pb = s_b;
    for (int d = 1; d < N_NODES; d <<= 1) {
        for (int i = t; i < N_NODES; i += 1024)
            pb[i] = pa[i] + (i >= d ? pa[i - d] : 0);
        __syncthreads();
        int* tmp = pa; pa = pb; pb = tmp;
    }
    for (int i = t; i < N_NODES; i += 1024) {
        int off = (i == 0) ? 0 : pa[i - 1];
        g_csr_off[i] = off;
        pb[i] = off;
    }
    if (t == 0) g_csr_off[N_NODES] = N_EDGES;
    __syncthreads();

    #pragma unroll
    for (int j = 0; j < 8; j++) {
        int e = t + 1024 * j;
        int pos = atomicAdd(&pb[es[j]], 1);
        g_csr_edge[pos] = e;
    }
}

// =====================================================================
// w2 -> g_At transpose (coalesced both sides via smem tile).
// =====================================================================
__global__ __launch_bounds__(256) void w2t_kernel(const float* __restrict__ w2a,
                                                  const float* __restrict__ w2b) {
    __shared__ float tile[HID][33];
    int b = blockIdx.x;           // 0..319
    int slot = b / 160;
    int rem = b % 160;
    int q = rem / 5;              // 0..31
    int ot = rem % 5;             // 0..4
    const float* w2 = slot ? w2b : w2a;
    int o0 = ot * 32;
    int lane = threadIdx.x & 31;
    int kr = threadIdx.x >> 5;
    for (int k = kr; k < HID; k += 8)
        tile[k][lane] = w2[q * NW + k * HID + o0 + lane];
    __syncthreads();
    __half* dst = g_At[slot];
    for (int idx = threadIdx.x; idx < 32 * HID; idx += 256) {
        int ol = idx / HID, k = idx % HID;
        dst[(size_t)(q * HID + o0 + ol) * HID + kp16(k)] = __float2half_rn(tile[k][ol]);
    }
}

// =====================================================================
// Params: b2/root into g_At + edge MLP h + zero accum + x convert.
// =====================================================================
#define BR_BLOCKS (2 * HID * HID / 256)              // 200 per slot
#define H_BLOCKS  (N_EDGES / 8)                      // 1024
#define Z_BLOCKS  (N_NODES * HID / 256)              // 1280
#define XC_BLOCKS (N_NODES * HID / 256)              // 1280

__global__ __launch_bounds__(256) void params_kernel(
        const float* __restrict__ b2a, const float* __restrict__ roota,
        const float* __restrict__ b2b, const float* __restrict__ rootb,
        const float* __restrict__ ea,
        const float* __restrict__ w1a, const float* __restrict__ b1a,
        const float* __restrict__ w1b, const float* __restrict__ b1b,
        const float* __restrict__ xin) {
    __shared__ float sw[EDGE_DIM * EH];
    __shared__ float sb[EH];
    int b = blockIdx.x;
    int t = threadIdx.x;

    if (b < 2 * BR_BLOCKS) {
        int slot = (b >= BR_BLOCKS);
        const float* b2   = slot ? b2b : b2a;
        const float* root = slot ? rootb : roota;
        int idx = (b - slot * BR_BLOCKS) * 256 + t;   // < 51200
        int c = COL_B2 + idx / HID;     // 5120..5439
        int k = idx % HID;
        float v = (c < COL_ROOT) ? b2[k * HID + (c - COL_B2)]
                                 : root[k * HID + (c - COL_ROOT)];
        g_At[slot][(size_t)c * HID + kp16(k)] = __float2half_rn(v);
        if (b == 0 || b == BR_BLOCKS) {
            for (int p = t; p < (NROWS_PAD - NCOLS) * HID; p += 256)
                g_At[slot][(size_t)NCOLS * HID + p] = __float2half_rn(0.0f);
        }
    } else if (b < 2 * BR_BLOCKS + 2 * H_BLOCKS) {
        int bb = b - 2 * BR_BLOCKS;
        int slot = (bb >= H_BLOCKS);
        const float* w1 = slot ? w1b : w1a;
        const float* b1 = slot ? b1b : b1a;
        for (int i = t; i < EDGE_DIM * EH; i += 256) sw[i] = w1[i];
        if (t < EH) sb[t] = b1[t];
        __syncthreads();
        int j  = t & 31;
        int e  = (bb - slot * H_BLOCKS) * 8 + (t >> 5);
        float acc = sb[j];
        #pragma unroll
        for (int d = 0; d < EDGE_DIM; d++)
            acc += ea[e * EDGE_DIM + d] * sw[d * EH + j];
        g_h[slot][e * EH + j] = fmaxf(acc, 0.0f);
    } else if (b < 2 * BR_BLOCKS + 2 * H_BLOCKS + Z_BLOCKS) {
        int idx = (b - 2 * BR_BLOCKS - 2 * H_BLOCKS) * 256 + t;
        g_accum[idx] = 0.0f;
    } else {
        int idx = (b - 2 * BR_BLOCKS - 2 * H_BLOCKS - Z_BLOCKS) * 256 + t;
        int n = idx / HID, o = idx % HID;
        g_x[1][n * HID + kp16(o)] = __float2half_rn(xin[idx]);
    }
}

// =====================================================================
// FP16 tensor GEMM with split-K-half staging pipeline:
// stage K[0,80) commit, K[80,160) commit; compute ks0-4 overlapped with
// the second half's transfer; then ks5-9.
// =====================================================================
#define BM 128
#define BN 128
#define SHS 208                       // halves; 104 words ≡ 8 (mod 32)
#define ATILE (BM * SHS)              // 26624 halves
#define GEMM_SMEM (2 * ATILE * 2)     // 106496 B

__device__ __forceinline__ void mma_f16(float* d, const uint32_t* a, const uint32_t* b) {
    asm volatile(
        "mma.sync.aligned.m16n8k16.row.col.f32.f16.f16.f32 "
        "{%0,%1,%2,%3}, {%4,%5,%6,%7}, {%8,%9}, {%0,%1,%2,%3};"
        : "+f"(d[0]), "+f"(d[1]), "+f"(d[2]), "+f"(d[3])
        : "r"(a[0]), "r"(a[1]), "r"(a[2]), "r"(a[3]), "r"(b[0]), "r"(b[1]));
}

__global__ __launch_bounds__(256, 2) void gemm_kernel(int xsel, int aslot) {
    const __half* __restrict__ X = g_x[xsel];
    const __half* __restrict__ W = g_At[aslot];

    extern __shared__ char smem_raw[];
    __half* As = (__half*)smem_raw;            // [ATILE]
    __half* Bs = As + ATILE;                   // [ATILE]

    int tid  = threadIdx.x;
    int lane = tid & 31;
    int w    = tid >> 5;
    int wm   = w & 1;
    int wn   = w >> 1;
    int g    = lane >> 2;
    int tig  = lane & 3;

    int n0 = blockIdx.x * BN;
    int m0 = blockIdx.y * BM;

    float acc[4][4][4];
    #pragma unroll
    for (int i = 0; i < 4; i++)
        #pragma unroll
        for (int j = 0; j < 4; j++)
            #pragma unroll
            for (int r = 0; r < 4; r++) acc[i][j][r] = 0.0f;

    // staged in two K-halves (chunks 0..9, then 10..19), two commit groups
    #pragma unroll
    for (int h = 0; h < 2; h++) {
        #pragma unroll
        for (int i = 0; i < 5; i++) {
            int s   = tid + 256 * i;          // 0..1279
            int row = s / 10;
            int ch  = ((s % 10) + h * 10) * 8;
            uint32_t dst = (uint32_t)__cvta_generic_to_shared(&As[row * SHS + ch]);
            const __half* src = X + (size_t)(m0 + row) * HID + ch;
            asm volatile("cp.async.cg.shared.global [%0], [%1], 16;"
                         :: "r"(dst), "l"(src));
        }
        #pragma unroll
        for (int i = 0; i < 5; i++) {
            int s   = tid + 256 * i;
            int row = s / 10;
            int ch  = ((s % 10) + h * 10) * 8;
            uint32_t dst = (uint32_t)__cvta_generic_to_shared(&Bs[row * SHS + ch]);
            const __half* src = W + (size_t)(n0 + row) * HID + ch;
            asm volatile("cp.async.cg.shared.global [%0], [%1], 16;"
                         :: "r"(dst), "l"(src));
        }
        asm volatile("cp.async.commit_group;");
    }

    #pragma unroll
    for (int half = 0; half < 2; half++) {
        if (half == 0) asm volatile("cp.async.wait_group 1;");
        else           asm volatile("cp.async.wait_group 0;");
        __syncthreads();
        #pragma unroll
        for (int ki = 0; ki < 5; ki++) {
            int ck = (half * 5 + ki) * 16;
            uint32_t af[4][4];
            #pragma unroll
            for (int mt = 0; mt < 4; mt++) {
                int rb = wm * 64 + mt * 16;
                uint2 lo = *(const uint2*)&As[(rb + g)     * SHS + ck + 4 * tig];
                uint2 hi = *(const uint2*)&As[(rb + g + 8) * SHS + ck + 4 * tig];
                af[mt][0] = lo.x;
                af[mt][1] = hi.x;
                af[mt][2] = lo.y;
                af[mt][3] = hi.y;
            }
            uint32_t bf[4][2];
            #pragma unroll
            for (int nt = 0; nt < 4; nt++) {
                int nc = wn * 32 + nt * 8 + g;
                uint2 bb = *(const uint2*)&Bs[nc * SHS + ck + 4 * tig];
                bf[nt][0] = bb.x;
                bf[nt][1] = bb.y;
            }
            #pragma unroll
            for (int mt = 0; mt < 4; mt++)
                #pragma unroll
                for (int nt = 0; nt < 4; nt++)
                    mma_f16(acc[mt][nt], af[mt], bf[nt]);
        }
    }

    // epilogue: msg/b2 cols -> fp16 g_Yh; root cols -> fp32 g_Yroot
    #pragma unroll
    for (int mt = 0; mt < 4; mt++) {
        int row = m0 + wm * 64 + mt * 16 + g;
        #pragma unroll
        for (int nt = 0; nt < 4; nt++) {
            int col = n0 + wn * 32 + nt * 8 + 2 * tig;
            if (col < COL_ROOT) {
                *(__half2*)&g_Yh[(size_t)row * COL_ROOT + col] =
                    __floats2half2_rn(acc[mt][nt][0], acc[mt][nt][1]);
                *(__half2*)&g_Yh[(size_t)(row + 8) * COL_ROOT + col] =
                    __floats2half2_rn(acc[mt][nt][2], acc[mt][nt][3]);
            } else if (col < NCOLS) {
                int rc = col - COL_ROOT;
                *(float2*)&g_Yroot[row * HID + rc] =
                    make_float2(acc[mt][nt][0], acc[mt][nt][1]);
                *(float2*)&g_Yroot[(row + 8) * HID + rc] =
                    make_float2(acc[mt][nt][2], acc[mt][nt][3]);
            }
        }
    }
}

// =====================================================================
// Edge message + scatter: 2 nodes per block, pipelined cp.async groups.
// Node p staged as commit-group p; wait_group 1 -> compute node 0 while
// node 1's Y is still in flight.
// =====================================================================
#define ECHUNK 32
#define EBLK (N_NODES / 2)            // 1024 blocks

__global__ __launch_bounds__(256) void edge_kernel(int slot) {
    __shared__ __align__(16) __half sYh[2][COL_ROOT];   // 21120 B
    __shared__ float sh[ECHUNK * EH];                   // 4096 B
    __shared__ int   sdst[ECHUNK];
    int t = threadIdx.x;

    // stage both nodes' Y rows as two commit groups
    #pragma unroll
    for (int p = 0; p < 2; p++) {
        int n = blockIdx.x + p * EBLK;
        if (g_csr_off[n] != g_csr_off[n + 1]) {
            const __half* src0 = g_Yh + (size_t)n * COL_ROOT;
            for (int i = t; i < COL_ROOT / 8; i += 256) {
                uint32_t dst = (uint32_t)__cvta_generic_to_shared(&sYh[p][i * 8]);
                asm volatile("cp.async.cg.shared.global [%0], [%1], 16;"
                             :: "r"(dst), "l"(src0 + i * 8));
            }
        }
        asm volatile("cp.async.commit_group;");
    }

    #pragma unroll
    for (int p = 0; p < 2; p++) {
        if (p == 0) asm volatile("cp.async.wait_group 1;");
        else        asm volatile("cp.async.wait_group 0;");
        int n = blockIdx.x + p * EBLK;
        int beg = g_csr_off[n];
        int end = g_csr_off[n + 1];
        if (beg == end) continue;
        const __half* Yp = sYh[p];

        for (int cb = beg; cb < end; cb += ECHUNK) {
            int m = min(end - cb, ECHUNK);
            for (int i = t; i < m * EH; i += 256) {
                int j = i >> 5, k = i & 31;
                int e = g_csr_edge[cb + j];
                sh[i] = g_h[slot][e * EH + k];
            }
            if (t < m) sdst[t] = g_dst[g_csr_edge[cb + t]];
            __syncthreads();

            for (int idx = t; idx < m * 40; idx += 256) {
                int j = idx / 40, c = (idx - j * 40) * 4;
                const float* hj = &sh[j * EH];
                float4 msg;
                {
                    uint2 v = *(const uint2*)&Yp[COL_B2 + c];
                    float2 a = __half22float2(((const __half2*)&v)[0]);
                    float2 b = __half22float2(((const __half2*)&v)[1]);
                    msg = make_float4(a.x, a.y, b.x, b.y);
                }
                #pragma unroll
                for (int k = 0; k < EH; k++) {
                    float hk = hj[k];
                    uint2 v = *(const uint2*)&Yp[k * HID + c];
                    float2 a = __half22float2(((const __half2*)&v)[0]);
                    float2 b = __half22float2(((const __half2*)&v)[1]);
                    msg.x += hk * a.x;
                    msg.y += hk * a.y;
                    msg.z += hk * b.x;
                    msg.w += hk * b.y;
                }
                atomicAdd((float4*)&g_accum[sdst[j] * HID + c], msg);
            }
            __syncthreads();
        }
    }
}

// =====================================================================
// Finalize: v = accum/max(cnt,1) + root(fp32) + bias; re-zero accum.
// =====================================================================
__global__ void final_kernel(const float* __restrict__ bias, int outsel,
                             float* __restrict__ dout, int relu) {
    int idx = blockIdx.x * blockDim.x + threadIdx.x;
    if (idx >= N_NODES * HID) return;
    int n = idx / HID, o = idx % HID;
    float inv = 1.0f / fmaxf((float)g_cnt[n], 1.0f);
    float v = g_accum[idx] * inv + g_Yroot[idx] + bias[o];
    if (relu) v = fmaxf(v, 0.0f);
    g_accum[idx] = 0.0f;
    if (outsel == 2) {
        dout[idx] = v;
    } else {
        g_x[outsel][n * HID + kp16(o)] = __float2half_rn(v);
    }
}

// =====================================================================
// launch
// =====================================================================
extern "C" void kernel_launch(void* const* d_in, const int* in_sizes, int n_in,
                              void* d_out, int out_size) {
    const float* x       = (const float*)d_in[0];
    const float* ea      = (const float*)d_in[1];
    const float* w1_a    = (const float*)d_in[2];
    const float* b1_a    = (const float*)d_in[3];
    const float* w2_a    = (const float*)d_in[4];
    const float* b2_a    = (const float*)d_in[5];
    const float* root_a  = (const float*)d_in[6];
    const float* bias_a  = (const float*)d_in[7];
    const float* w1_b    = (const float*)d_in[8];
    const float* b1_b    = (const float*)d_in[9];
    const float* w2_b    = (const float*)d_in[10];
    const float* b2_b    = (const float*)d_in[11];
    const float* root_b  = (const float*)d_in[12];
    const float* bias_b  = (const float*)d_in[13];
    const void*  eidx    = d_in[14];
    float* out = (float*)d_out;

    static int smem_set = 0;
    if (!smem_set) {
        cudaFuncSetAttribute(gemm_kernel,
                             cudaFuncAttributeMaxDynamicSharedMemorySize, GEMM_SMEM);
        smem_set = 1;
    }

    prep_kernel<<<1, 1024>>>(eidx);
    w2t_kernel<<<320, 256>>>(w2_a, w2_b);
    params_kernel<<<2 * BR_BLOCKS + 2 * H_BLOCKS + Z_BLOCKS + XC_BLOCKS, 256>>>(
        b2_a, root_a, b2_b, root_b, ea, w1_a, b1_a, w1_b, b1_b, x);

    dim3 gemm_grid(NROWS_PAD / BN, N_NODES / BM);   // (43, 16)
    int fb = (N_NODES * HID + 255) / 256;

    // layer 0 (params a), relu — converted input lives in g_x[1]
    gemm_kernel<<<gemm_grid, 256, GEMM_SMEM>>>(1, 0);
    edge_kernel<<<EBLK, 256>>>(0);
    final_kernel<<<fb, 256>>>(bias_a, 0, out, 1);

    // layer 1 (params b), relu
    gemm_kernel<<<gemm_grid, 256, GEMM_SMEM>>>(0, 1);
    edge_kernel<<<EBLK, 256>>>(1);
    final_kernel<<<fb, 256>>>(bias_b, 1, out, 1);

    // layer 2 (params b), no relu -> d_out
    gemm_kernel<<<gemm_grid, 256, GEMM_SMEM>>>(1, 1);
    edge_kernel<<<EBLK, 256>>>(1);
    final_kernel<<<fb, 256>>>(bias_b, 2, out, 0);
}

// round 16
// speedup vs baseline: 1.0643x; 1.0643x over previous
#include <cuda_runtime.h>
#include <cuda_fp16.h>
#include <cstdint>

#define N_NODES 2048
#define N_EDGES 8192
#define EDGE_DIM 10
#define EH 32
#define HID 160
#define NW (HID*HID)                 // 25600
#define COL_B2 (EH*HID)              // 5120
#define COL_ROOT (EH*HID + HID)      // 5280
#define NCOLS (EH*HID + HID + HID)   // 5440
#define NROWS_PAD 5504               // NCOLS padded to 128 multiple

// fp16 k-permutation within 16-blocks: thread tig reads orig k
// {2t,2t+1,8+2t,8+2t+1} as 4 contiguous halves at pos 4t..4t+3.
__host__ __device__ __forceinline__ int kp16(int k) {
    return (k & ~15) | (((k & 7) >> 1) << 2) | ((k & 8) >> 2) | (k & 1);
}

// ---------------- device scratch ----------------
__device__ __half g_At[2][NROWS_PAD * HID];     // W^T [n][k], kp16 cols, fp16
__device__ __half g_x[2][N_NODES * HID];        // features, kp16 cols, fp16
__device__ __half g_Yh[(size_t)N_NODES * COL_ROOT]; // Y msg+b2 cols, fp16
__device__ float  g_Yroot[N_NODES * HID];       // Y root cols, fp32
__device__ float  g_h[2][N_EDGES * EH];
__device__ float  g_accum[N_NODES * HID];
__device__ int    g_cnt[N_NODES];
__device__ int    g_dst[N_EDGES];
__device__ int    g_csr_off[N_NODES + 1];
__device__ int    g_csr_edge[N_EDGES];

// =====================================================================
// Preprocessing (one block)
// =====================================================================
__global__ __launch_bounds__(1024) void prep_kernel(const void* __restrict__ eiraw) {
    __shared__ int s_flag;
    __shared__ int s_cs[N_NODES];
    __shared__ int s_cd[N_NODES];
    __shared__ int s_a[N_NODES];
    __shared__ int s_b[N_NODES];
    int t = threadIdx.x;

    for (int i = t; i < N_NODES; i += 1024) { s_cs[i] = 0; s_cd[i] = 0; }
    if (t == 0) s_flag = 0;
    __syncthreads();

    const int* raw = (const int*)eiraw;
    int f = 0;
    for (int i = t; i < N_EDGES; i += 1024)
        if (raw[2 * i + 1] != 0) f = 1;
    if (f) atomicOr(&s_flag, 1);
    __syncthreads();
    int flag = s_flag;

    int es[8], ed[8];
    #pragma unroll
    for (int j = 0; j < 8; j++) {
        int e = t + 1024 * j;
        if (flag) {
            es[j] = raw[e]; ed[j] = raw[N_EDGES + e];
        } else {
            const long long* p = (const long long*)eiraw;
            es[j] = (int)p[e]; ed[j] = (int)p[N_EDGES + e];
        }
        atomicAdd(&s_cs[es[j]], 1);
        atomicAdd(&s_cd[ed[j]], 1);
        g_dst[e] = ed[j];
    }
    __syncthreads();

    for (int i = t; i < N_NODES; i += 1024) { g_cnt[i] = s_cd[i]; s_a[i] = s_cs[i]; }
    __syncthreads();

    int* pa = s_a; int* pb = s_b;
    for (int d = 1; d < N_NODES; d <<= 1) {
        for (int i = t; i < N_NODES; i += 1024)
            pb[i] = pa[i] + (i >= d ? pa[i - d] : 0);
        __syncthreads();
        int* tmp = pa; pa = pb; pb = tmp;
    }
    for (int i = t; i < N_NODES; i += 1024) {
        int off = (i == 0) ? 0 : pa[i - 1];
        g_csr_off[i] = off;
        pb[i] = off;
    }
    if (t == 0) g_csr_off[N_NODES] = N_EDGES;
    __syncthreads();

    #pragma unroll
    for (int j = 0; j < 8; j++) {
        int e = t + 1024 * j;
        int pos = atomicAdd(&pb[es[j]], 1);
        g_csr_edge[pos] = e;
    }
}

// =====================================================================
// Params mega-kernel: w2 transpose tiles + b2/root into g_At + edge MLP
// h + zero accum + x convert. One launch.
// =====================================================================
#define W2T_BLOCKS 320                               // 2 slots x 32 q x 5 otiles
#define BR_BLOCKS (2 * HID * HID / 256)              // 200 per slot
#define H_BLOCKS  (N_EDGES / 8)                      // 1024
#define Z_BLOCKS  (N_NODES * HID / 256)              // 1280
#define XC_BLOCKS (N_NODES * HID / 256)              // 1280

__global__ __launch_bounds__(256) void params_kernel(
        const float* __restrict__ w2a, const float* __restrict__ w2b,
        const float* __restrict__ b2a, const float* __restrict__ roota,
        const float* __restrict__ b2b, const float* __restrict__ rootb,
        const float* __restrict__ ea,
        const float* __restrict__ w1a, const float* __restrict__ b1a,
        const float* __restrict__ w1b, const float* __restrict__ b1b,
        const float* __restrict__ xin) {
    __shared__ float tile[HID][33];    // w2t branch (21 KB)
    int b = blockIdx.x;
    int t = threadIdx.x;

    if (b < W2T_BLOCKS) {
        int slot = b / 160;
        int rem = b % 160;
        int q = rem / 5;              // 0..31
        int ot = rem % 5;             // 0..4
        const float* w2 = slot ? w2b : w2a;
        int o0 = ot * 32;
        int lane = t & 31;
        int kr = t >> 5;
        for (int k = kr; k < HID; k += 8)
            tile[k][lane] = w2[q * NW + k * HID + o0 + lane];
        __syncthreads();
        __half* dst = g_At[slot];
        for (int idx = t; idx < 32 * HID; idx += 256) {
            int ol = idx / HID, k = idx % HID;
            dst[(size_t)(q * HID + o0 + ol) * HID + kp16(k)] =
                __float2half_rn(tile[k][ol]);
        }
    } else if (b < W2T_BLOCKS + 2 * BR_BLOCKS) {
        int bb = b - W2T_BLOCKS;
        int slot = (bb >= BR_BLOCKS);
        const float* b2   = slot ? b2b : b2a;
        const float* root = slot ? rootb : roota;
        int idx = (bb - slot * BR_BLOCKS) * 256 + t;   // < 51200
        int c = COL_B2 + idx / HID;     // 5120..5439
        int k = idx % HID;
        float v = (c < COL_ROOT) ? b2[k * HID + (c - COL_B2)]
                                 : root[k * HID + (c - COL_ROOT)];
        g_At[slot][(size_t)c * HID + kp16(k)] = __float2half_rn(v);
        if (bb == 0 || bb == BR_BLOCKS) {
            for (int p = t; p < (NROWS_PAD - NCOLS) * HID; p += 256)
                g_At[slot][(size_t)NCOLS * HID + p] = __float2half_rn(0.0f);
        }
    } else if (b < W2T_BLOCKS + 2 * BR_BLOCKS + 2 * H_BLOCKS) {
        __shared__ float sw[EDGE_DIM * EH];
        __shared__ float sb[EH];
        int bb = b - W2T_BLOCKS - 2 * BR_BLOCKS;
        int slot = (bb >= H_BLOCKS);
        const float* w1 = slot ? w1b : w1a;
        const float* b1 = slot ? b1b : b1a;
        for (int i = t; i < EDGE_DIM * EH; i += 256) sw[i] = w1[i];
        if (t < EH) sb[t] = b1[t];
        __syncthreads();
        int j  = t & 31;
        int e  = (bb - slot * H_BLOCKS) * 8 + (t >> 5);
        float acc = sb[j];
        #pragma unroll
        for (int d = 0; d < EDGE_DIM; d++)
            acc += ea[e * EDGE_DIM + d] * sw[d * EH + j];
        g_h[slot][e * EH + j] = fmaxf(acc, 0.0f);
    } else if (b < W2T_BLOCKS + 2 * BR_BLOCKS + 2 * H_BLOCKS + Z_BLOCKS) {
        int idx = (b - W2T_BLOCKS - 2 * BR_BLOCKS - 2 * H_BLOCKS) * 256 + t;
        g_accum[idx] = 0.0f;
    } else {
        int idx = (b - W2T_BLOCKS - 2 * BR_BLOCKS - 2 * H_BLOCKS - Z_BLOCKS) * 256 + t;
        int n = idx / HID, o = idx % HID;
        g_x[1][n * HID + kp16(o)] = __float2half_rn(xin[idx]);
    }
}

// =====================================================================
// FP16 tensor GEMM, single-stage (R14, best measured): full K=160
// staged once, 10 straight-line k-groups, one syncthreads.
// =====================================================================
#define BM 128
#define BN 128
#define SHS 208                       // halves; 104 words ≡ 8 (mod 32)
#define ATILE (BM * SHS)              // 26624 halves
#define GEMM_SMEM (2 * ATILE * 2)     // 106496 B

__device__ __forceinline__ void mma_f16(float* d, const uint32_t* a, const uint32_t* b) {
    asm volatile(
        "mma.sync.aligned.m16n8k16.row.col.f32.f16.f16.f32 "
        "{%0,%1,%2,%3}, {%4,%5,%6,%7}, {%8,%9}, {%0,%1,%2,%3};"
        : "+f"(d[0]), "+f"(d[1]), "+f"(d[2]), "+f"(d[3])
        : "r"(a[0]), "r"(a[1]), "r"(a[2]), "r"(a[3]), "r"(b[0]), "r"(b[1]));
}

__global__ __launch_bounds__(256, 2) void gemm_kernel(int xsel, int aslot) {
    const __half* __restrict__ X = g_x[xsel];
    const __half* __restrict__ W = g_At[aslot];

    extern __shared__ char smem_raw[];
    __half* As = (__half*)smem_raw;            // [ATILE]
    __half* Bs = As + ATILE;                   // [ATILE]

    int tid  = threadIdx.x;
    int lane = tid & 31;
    int w    = tid >> 5;
    int wm   = w & 1;
    int wn   = w >> 1;
    int g    = lane >> 2;
    int tig  = lane & 3;

    int n0 = blockIdx.x * BN;
    int m0 = blockIdx.y * BM;

    float acc[4][4][4];
    #pragma unroll
    for (int i = 0; i < 4; i++)
        #pragma unroll
        for (int j = 0; j < 4; j++)
            #pragma unroll
            for (int r = 0; r < 4; r++) acc[i][j][r] = 0.0f;

    // stage full K: 128 rows x 20 chunks (16B) per tile, 10 per thread each
    #pragma unroll
    for (int i = 0; i < 10; i++) {
        int s   = tid + 256 * i;              // 0..2559
        int row = s / 20;
        int ch  = (s % 20) * 8;
        uint32_t dst = (uint32_t)__cvta_generic_to_shared(&As[row * SHS + ch]);
        const __half* src = X + (size_t)(m0 + row) * HID + ch;
        asm volatile("cp.async.cg.shared.global [%0], [%1], 16;"
                     :: "r"(dst), "l"(src));
    }
    #pragma unroll
    for (int i = 0; i < 10; i++) {
        int s   = tid + 256 * i;
        int row = s / 20;
        int ch  = (s % 20) * 8;
        uint32_t dst = (uint32_t)__cvta_generic_to_shared(&Bs[row * SHS + ch]);
        const __half* src = W + (size_t)(n0 + row) * HID + ch;
        asm volatile("cp.async.cg.shared.global [%0], [%1], 16;"
                     :: "r"(dst), "l"(src));
    }
    asm volatile("cp.async.commit_group;");
    asm volatile("cp.async.wait_group 0;");
    __syncthreads();

    // straight-line mainloop: 10 k-groups of 16
    #pragma unroll
    for (int ks = 0; ks < 10; ks++) {
        int ck = ks * 16;
        uint32_t af[4][4];
        #pragma unroll
        for (int mt = 0; mt < 4; mt++) {
            int rb = wm * 64 + mt * 16;
            uint2 lo = *(const uint2*)&As[(rb + g)     * SHS + ck + 4 * tig];
            uint2 hi = *(const uint2*)&As[(rb + g + 8) * SHS + ck + 4 * tig];
            af[mt][0] = lo.x;
            af[mt][1] = hi.x;
            af[mt][2] = lo.y;
            af[mt][3] = hi.y;
        }
        uint32_t bf[4][2];
        #pragma unroll
        for (int nt = 0; nt < 4; nt++) {
            int nc = wn * 32 + nt * 8 + g;
            uint2 bb = *(const uint2*)&Bs[nc * SHS + ck + 4 * tig];
            bf[nt][0] = bb.x;
            bf[nt][1] = bb.y;
        }
        #pragma unroll
        for (int mt = 0; mt < 4; mt++)
            #pragma unroll
            for (int nt = 0; nt < 4; nt++)
                mma_f16(acc[mt][nt], af[mt], bf[nt]);
    }

    // epilogue: msg/b2 cols -> fp16 g_Yh; root cols -> fp32 g_Yroot
    #pragma unroll
    for (int mt = 0; mt < 4; mt++) {
        int row = m0 + wm * 64 + mt * 16 + g;
        #pragma unroll
        for (int nt = 0; nt < 4; nt++) {
            int col = n0 + wn * 32 + nt * 8 + 2 * tig;
            if (col < COL_ROOT) {
                *(__half2*)&g_Yh[(size_t)row * COL_ROOT + col] =
                    __floats2half2_rn(acc[mt][nt][0], acc[mt][nt][1]);
                *(__half2*)&g_Yh[(size_t)(row + 8) * COL_ROOT + col] =
                    __floats2half2_rn(acc[mt][nt][2], acc[mt][nt][3]);
            } else if (col < NCOLS) {
                int rc = col - COL_ROOT;
                *(float2*)&g_Yroot[row * HID + rc] =
                    make_float2(acc[mt][nt][0], acc[mt][nt][1]);
                *(float2*)&g_Yroot[(row + 8) * HID + rc] =
                    make_float2(acc[mt][nt][2], acc[mt][nt][3]);
            }
        }
    }
}

// =====================================================================
// Edge message + scatter: 128 threads, ECHUNK=16 -> ~12.7 KB smem ->
// 16 blocks/SM (full occupancy), 2048 blocks in <1 wave.
// =====================================================================
#define ECHUNK 16
#define ETHR 128

__global__ __launch_bounds__(ETHR) void edge_kernel(int slot) {
    __shared__ __align__(16) __half sYh[COL_ROOT];   // 10560 B
    __shared__ float sh[ECHUNK * EH];                // 2048 B
    __shared__ int   sdst[ECHUNK];
    int n = blockIdx.x;
    int t = threadIdx.x;
    int beg = g_csr_off[n];
    int end = g_csr_off[n + 1];
    if (beg == end) return;

    const __half* src0 = g_Yh + (size_t)n * COL_ROOT;
    for (int i = t; i < COL_ROOT / 8; i += ETHR) {
        uint32_t dst = (uint32_t)__cvta_generic_to_shared(&sYh[i * 8]);
        asm volatile("cp.async.cg.shared.global [%0], [%1], 16;"
                     :: "r"(dst), "l"(src0 + i * 8));
    }
    asm volatile("cp.async.commit_group;");

    bool first = true;
    for (int cb = beg; cb < end; cb += ECHUNK) {
        int m = min(end - cb, ECHUNK);
        for (int i = t; i < m * EH; i += ETHR) {
            int j = i >> 5, k = i & 31;
            int e = g_csr_edge[cb + j];
            sh[i] = g_h[slot][e * EH + k];
        }
        if (t < m) sdst[t] = g_dst[g_csr_edge[cb + t]];
        if (first) {
            asm volatile("cp.async.wait_group 0;");
            first = false;
        }
        __syncthreads();

        for (int idx = t; idx < m * 40; idx += ETHR) {
            int j = idx / 40, c = (idx - j * 40) * 4;
            const float* hj = &sh[j * EH];
            float4 msg;
            {
                uint2 v = *(const uint2*)&sYh[COL_B2 + c];
                float2 a = __half22float2(((const __half2*)&v)[0]);
                float2 b = __half22float2(((const __half2*)&v)[1]);
                msg = make_float4(a.x, a.y, b.x, b.y);
            }
            #pragma unroll
            for (int k = 0; k < EH; k++) {
                float hk = hj[k];
                uint2 v = *(const uint2*)&sYh[k * HID + c];
                float2 a = __half22float2(((const __half2*)&v)[0]);
                float2 b = __half22float2(((const __half2*)&v)[1]);
                msg.x += hk * a.x;
                msg.y += hk * a.y;
                msg.z += hk * b.x;
                msg.w += hk * b.y;
            }
            atomicAdd((float4*)&g_accum[sdst[j] * HID + c], msg);
        }
        __syncthreads();
    }
}

// =====================================================================
// Finalize: v = accum/max(cnt,1) + root(fp32) + bias; re-zero accum.
// =====================================================================
__global__ void final_kernel(const float* __restrict__ bias, int outsel,
                             float* __restrict__ dout, int relu) {
    int idx = blockIdx.x * blockDim.x + threadIdx.x;
    if (idx >= N_NODES * HID) return;
    int n = idx / HID, o = idx % HID;
    float inv = 1.0f / fmaxf((float)g_cnt[n], 1.0f);
    float v = g_accum[idx] * inv + g_Yroot[idx] + bias[o];
    if (relu) v = fmaxf(v, 0.0f);
    g_accum[idx] = 0.0f;
    if (outsel == 2) {
        dout[idx] = v;
    } else {
        g_x[outsel][n * HID + kp16(o)] = __float2half_rn(v);
    }
}

// =====================================================================
// launch
// =====================================================================
extern "C" void kernel_launch(void* const* d_in, const int* in_sizes, int n_in,
                              void* d_out, int out_size) {
    const float* x       = (const float*)d_in[0];
    const float* ea      = (const float*)d_in[1];
    const float* w1_a    = (const float*)d_in[2];
    const float* b1_a    = (const float*)d_in[3];
    const float* w2_a    = (const float*)d_in[4];
    const float* b2_a    = (const float*)d_in[5];
    const float* root_a  = (const float*)d_in[6];
    const float* bias_a  = (const float*)d_in[7];
    const float* w1_b    = (const float*)d_in[8];
    const float* b1_b    = (const float*)d_in[9];
    const float* w2_b    = (const float*)d_in[10];
    const float* b2_b    = (const float*)d_in[11];
    const float* root_b  = (const float*)d_in[12];
    const float* bias_b  = (const float*)d_in[13];
    const void*  eidx    = d_in[14];
    float* out = (float*)d_out;

    static int smem_set = 0;
    if (!smem_set) {
        cudaFuncSetAttribute(gemm_kernel,
                             cudaFuncAttributeMaxDynamicSharedMemorySize, GEMM_SMEM);
        smem_set = 1;
    }

    prep_kernel<<<1, 1024>>>(eidx);
    params_kernel<<<W2T_BLOCKS + 2 * BR_BLOCKS + 2 * H_BLOCKS + Z_BLOCKS + XC_BLOCKS, 256>>>(
        w2_a, w2_b, b2_a, root_a, b2_b, root_b, ea, w1_a, b1_a, w1_b, b1_b, x);

    dim3 gemm_grid(NROWS_PAD / BN, N_NODES / BM);   // (43, 16)
    int fb = (N_NODES * HID + 255) / 256;

    // layer 0 (params a), relu — converted input lives in g_x[1]
    gemm_kernel<<<gemm_grid, 256, GEMM_SMEM>>>(1, 0);
    edge_kernel<<<N_NODES, ETHR>>>(0);
    final_kernel<<<fb, 256>>>(bias_a, 0, out, 1);

    // layer 1 (params b), relu
    gemm_kernel<<<gemm_grid, 256, GEMM_SMEM>>>(0, 1);
    edge_kernel<<<N_NODES, ETHR>>>(1);
    final_kernel<<<fb, 256>>>(bias_b, 1, out, 1);

    // layer 2 (params b), no relu -> d_out
    gemm_kernel<<<gemm_grid, 256, GEMM_SMEM>>>(1, 1);
    edge_kernel<<<N_NODES, ETHR>>>(1);
    final_kernel<<<fb, 256>>>(bias_b, 2, out, 0);
}

// round 17
// speedup vs baseline: 1.1162x; 1.0487x over previous
#include <cuda_runtime.h>
#include <cuda_fp16.h>
#include <cstdint>

#define N_NODES 2048
#define N_EDGES 8192
#define EDGE_DIM 10
#define EH 32
#define HID 160
#define NW (HID*HID)                 // 25600
#define COL_B2 (EH*HID)              // 5120
#define COL_ROOT (EH*HID + HID)      // 5280
#define NCOLS (EH*HID + HID + HID)   // 5440
#define NROWS_PAD 5504               // NCOLS padded to 128 multiple

// fp16 k-permutation within 16-blocks: thread tig reads orig k
// {2t,2t+1,8+2t,8+2t+1} as 4 contiguous halves at pos 4t..4t+3.
__host__ __device__ __forceinline__ int kp16(int k) {
    return (k & ~15) | (((k & 7) >> 1) << 2) | ((k & 8) >> 2) | (k & 1);
}

// ---------------- device scratch ----------------
__device__ __half g_At[2][NROWS_PAD * HID];     // W^T [n][k], kp16 cols, fp16
__device__ __half g_x[2][N_NODES * HID];        // features, kp16 cols, fp16
__device__ __half g_Yh[(size_t)N_NODES * COL_ROOT]; // Y msg+b2 cols, fp16
__device__ float  g_Yroot[N_NODES * HID];       // Y root cols, fp32
__device__ float  g_h[2][N_EDGES * EH];
__device__ float  g_accum[N_NODES * HID];
__device__ int    g_cnt[N_NODES];
__device__ int    g_dst[N_EDGES];
__device__ int    g_csr_off[N_NODES + 1];
__device__ int    g_csr_edge[N_EDGES];

// =====================================================================
// Preprocessing (one block) — runs CONCURRENTLY with params_kernel.
// =====================================================================
__global__ __launch_bounds__(1024) void prep_kernel(const void* __restrict__ eiraw) {
    __shared__ int s_flag;
    __shared__ int s_cs[N_NODES];
    __shared__ int s_cd[N_NODES];
    __shared__ int s_a[N_NODES];
    __shared__ int s_b[N_NODES];
    int t = threadIdx.x;

    for (int i = t; i < N_NODES; i += 1024) { s_cs[i] = 0; s_cd[i] = 0; }
    if (t == 0) s_flag = 0;
    __syncthreads();

    const int* raw = (const int*)eiraw;
    int f = 0;
    for (int i = t; i < N_EDGES; i += 1024)
        if (raw[2 * i + 1] != 0) f = 1;
    if (f) atomicOr(&s_flag, 1);
    __syncthreads();
    int flag = s_flag;

    int es[8], ed[8];
    #pragma unroll
    for (int j = 0; j < 8; j++) {
        int e = t + 1024 * j;
        if (flag) {
            es[j] = raw[e]; ed[j] = raw[N_EDGES + e];
        } else {
            const long long* p = (const long long*)eiraw;
            es[j] = (int)p[e]; ed[j] = (int)p[N_EDGES + e];
        }
        atomicAdd(&s_cs[es[j]], 1);
        atomicAdd(&s_cd[ed[j]], 1);
        g_dst[e] = ed[j];
    }
    __syncthreads();

    for (int i = t; i < N_NODES; i += 1024) { g_cnt[i] = s_cd[i]; s_a[i] = s_cs[i]; }
    __syncthreads();

    int* pa = s_a; int* pb = s_b;
    for (int d = 1; d < N_NODES; d <<= 1) {
        for (int i = t; i < N_NODES; i += 1024)
            pb[i] = pa[i] + (i >= d ? pa[i - d] : 0);
        __syncthreads();
        int* tmp = pa; pa = pb; pb = tmp;
    }
    for (int i = t; i < N_NODES; i += 1024) {
        int off = (i == 0) ? 0 : pa[i - 1];
        g_csr_off[i] = off;
        pb[i] = off;
    }
    if (t == 0) g_csr_off[N_NODES] = N_EDGES;
    __syncthreads();

    #pragma unroll
    for (int j = 0; j < 8; j++) {
        int e = t + 1024 * j;
        int pos = atomicAdd(&pb[es[j]], 1);
        g_csr_edge[pos] = e;
    }
}

// =====================================================================
// Params mega-kernel: w2 transpose tiles + b2/root into g_At + edge MLP
// h + zero accum + x convert. One launch.
// =====================================================================
#define W2T_BLOCKS 320                               // 2 slots x 32 q x 5 otiles
#define BR_BLOCKS (2 * HID * HID / 256)              // 200 per slot
#define H_BLOCKS  (N_EDGES / 8)                      // 1024
#define Z_BLOCKS  (N_NODES * HID / 256)              // 1280
#define XC_BLOCKS (N_NODES * HID / 256)              // 1280

__global__ __launch_bounds__(256) void params_kernel(
        const float* __restrict__ w2a, const float* __restrict__ w2b,
        const float* __restrict__ b2a, const float* __restrict__ roota,
        const float* __restrict__ b2b, const float* __restrict__ rootb,
        const float* __restrict__ ea,
        const float* __restrict__ w1a, const float* __restrict__ b1a,
        const float* __restrict__ w1b, const float* __restrict__ b1b,
        const float* __restrict__ xin) {
    __shared__ float tile[HID][33];    // w2t branch (21 KB)
    int b = blockIdx.x;
    int t = threadIdx.x;

    if (b < W2T_BLOCKS) {
        int slot = b / 160;
        int rem = b % 160;
        int q = rem / 5;              // 0..31
        int ot = rem % 5;             // 0..4
        const float* w2 = slot ? w2b : w2a;
        int o0 = ot * 32;
        int lane = t & 31;
        int kr = t >> 5;
        for (int k = kr; k < HID; k += 8)
            tile[k][lane] = w2[q * NW + k * HID + o0 + lane];
        __syncthreads();
        __half* dst = g_At[slot];
        for (int idx = t; idx < 32 * HID; idx += 256) {
            int ol = idx / HID, k = idx % HID;
            dst[(size_t)(q * HID + o0 + ol) * HID + kp16(k)] =
                __float2half_rn(tile[k][ol]);
        }
    } else if (b < W2T_BLOCKS + 2 * BR_BLOCKS) {
        int bb = b - W2T_BLOCKS;
        int slot = (bb >= BR_BLOCKS);
        const float* b2   = slot ? b2b : b2a;
        const float* root = slot ? rootb : roota;
        int idx = (bb - slot * BR_BLOCKS) * 256 + t;   // < 51200
        int c = COL_B2 + idx / HID;     // 5120..5439
        int k = idx % HID;
        float v = (c < COL_ROOT) ? b2[k * HID + (c - COL_B2)]
                                 : root[k * HID + (c - COL_ROOT)];
        g_At[slot][(size_t)c * HID + kp16(k)] = __float2half_rn(v);
        if (bb == 0 || bb == BR_BLOCKS) {
            for (int p = t; p < (NROWS_PAD - NCOLS) * HID; p += 256)
                g_At[slot][(size_t)NCOLS * HID + p] = __float2half_rn(0.0f);
        }
    } else if (b < W2T_BLOCKS + 2 * BR_BLOCKS + 2 * H_BLOCKS) {
        __shared__ float sw[EDGE_DIM * EH];
        __shared__ float sb[EH];
        int bb = b - W2T_BLOCKS - 2 * BR_BLOCKS;
        int slot = (bb >= H_BLOCKS);
        const float* w1 = slot ? w1b : w1a;
        const float* b1 = slot ? b1b : b1a;
        for (int i = t; i < EDGE_DIM * EH; i += 256) sw[i] = w1[i];
        if (t < EH) sb[t] = b1[t];
        __syncthreads();
        int j  = t & 31;
        int e  = (bb - slot * H_BLOCKS) * 8 + (t >> 5);
        float acc = sb[j];
        #pragma unroll
        for (int d = 0; d < EDGE_DIM; d++)
            acc += ea[e * EDGE_DIM + d] * sw[d * EH + j];
        g_h[slot][e * EH + j] = fmaxf(acc, 0.0f);
    } else if (b < W2T_BLOCKS + 2 * BR_BLOCKS + 2 * H_BLOCKS + Z_BLOCKS) {
        int idx = (b - W2T_BLOCKS - 2 * BR_BLOCKS - 2 * H_BLOCKS) * 256 + t;
        g_accum[idx] = 0.0f;
    } else {
        int idx = (b - W2T_BLOCKS - 2 * BR_BLOCKS - 2 * H_BLOCKS - Z_BLOCKS) * 256 + t;
        int n = idx / HID, o = idx % HID;
        g_x[1][n * HID + kp16(o)] = __float2half_rn(xin[idx]);
    }
}

// =====================================================================
// FP16 tensor GEMM, single-stage (R14 best): full K=160 staged once,
// 10 straight-line k-groups, one syncthreads.
// =====================================================================
#define BM 128
#define BN 128
#define SHS 208                       // halves; 104 words ≡ 8 (mod 32)
#define ATILE (BM * SHS)              // 26624 halves
#define GEMM_SMEM (2 * ATILE * 2)     // 106496 B

__device__ __forceinline__ void mma_f16(float* d, const uint32_t* a, const uint32_t* b) {
    asm volatile(
        "mma.sync.aligned.m16n8k16.row.col.f32.f16.f16.f32 "
        "{%0,%1,%2,%3}, {%4,%5,%6,%7}, {%8,%9}, {%0,%1,%2,%3};"
        : "+f"(d[0]), "+f"(d[1]), "+f"(d[2]), "+f"(d[3])
        : "r"(a[0]), "r"(a[1]), "r"(a[2]), "r"(a[3]), "r"(b[0]), "r"(b[1]));
}

__global__ __launch_bounds__(256, 2) void gemm_kernel(int xsel, int aslot) {
    const __half* __restrict__ X = g_x[xsel];
    const __half* __restrict__ W = g_At[aslot];

    extern __shared__ char smem_raw[];
    __half* As = (__half*)smem_raw;            // [ATILE]
    __half* Bs = As + ATILE;                   // [ATILE]

    int tid  = threadIdx.x;
    int lane = tid & 31;
    int w    = tid >> 5;
    int wm   = w & 1;
    int wn   = w >> 1;
    int g    = lane >> 2;
    int tig  = lane & 3;

    int n0 = blockIdx.x * BN;
    int m0 = blockIdx.y * BM;

    float acc[4][4][4];
    #pragma unroll
    for (int i = 0; i < 4; i++)
        #pragma unroll
        for (int j = 0; j < 4; j++)
            #pragma unroll
            for (int r = 0; r < 4; r++) acc[i][j][r] = 0.0f;

    #pragma unroll
    for (int i = 0; i < 10; i++) {
        int s   = tid + 256 * i;              // 0..2559
        int row = s / 20;
        int ch  = (s % 20) * 8;
        uint32_t dst = (uint32_t)__cvta_generic_to_shared(&As[row * SHS + ch]);
        const __half* src = X + (size_t)(m0 + row) * HID + ch;
        asm volatile("cp.async.cg.shared.global [%0], [%1], 16;"
                     :: "r"(dst), "l"(src));
    }
    #pragma unroll
    for (int i = 0; i < 10; i++) {
        int s   = tid + 256 * i;
        int row = s / 20;
        int ch  = (s % 20) * 8;
        uint32_t dst = (uint32_t)__cvta_generic_to_shared(&Bs[row * SHS + ch]);
        const __half* src = W + (size_t)(n0 + row) * HID + ch;
        asm volatile("cp.async.cg.shared.global [%0], [%1], 16;"
                     :: "r"(dst), "l"(src));
    }
    asm volatile("cp.async.commit_group;");
    asm volatile("cp.async.wait_group 0;");
    __syncthreads();

    #pragma unroll
    for (int ks = 0; ks < 10; ks++) {
        int ck = ks * 16;
        uint32_t af[4][4];
        #pragma unroll
        for (int mt = 0; mt < 4; mt++) {
            int rb = wm * 64 + mt * 16;
            uint2 lo = *(const uint2*)&As[(rb + g)     * SHS + ck + 4 * tig];
            uint2 hi = *(const uint2*)&As[(rb + g + 8) * SHS + ck + 4 * tig];
            af[mt][0] = lo.x;
            af[mt][1] = hi.x;
            af[mt][2] = lo.y;
            af[mt][3] = hi.y;
        }
        uint32_t bf[4][2];
        #pragma unroll
        for (int nt = 0; nt < 4; nt++) {
            int nc = wn * 32 + nt * 8 + g;
            uint2 bb = *(const uint2*)&Bs[nc * SHS + ck + 4 * tig];
            bf[nt][0] = bb.x;
            bf[nt][1] = bb.y;
        }
        #pragma unroll
        for (int mt = 0; mt < 4; mt++)
            #pragma unroll
            for (int nt = 0; nt < 4; nt++)
                mma_f16(acc[mt][nt], af[mt], bf[nt]);
    }

    #pragma unroll
    for (int mt = 0; mt < 4; mt++) {
        int row = m0 + wm * 64 + mt * 16 + g;
        #pragma unroll
        for (int nt = 0; nt < 4; nt++) {
            int col = n0 + wn * 32 + nt * 8 + 2 * tig;
            if (col < COL_ROOT) {
                *(__half2*)&g_Yh[(size_t)row * COL_ROOT + col] =
                    __floats2half2_rn(acc[mt][nt][0], acc[mt][nt][1]);
                *(__half2*)&g_Yh[(size_t)(row + 8) * COL_ROOT + col] =
                    __floats2half2_rn(acc[mt][nt][2], acc[mt][nt][3]);
            } else if (col < NCOLS) {
                int rc = col - COL_ROOT;
                *(float2*)&g_Yroot[row * HID + rc] =
                    make_float2(acc[mt][nt][0], acc[mt][nt][1]);
                *(float2*)&g_Yroot[(row + 8) * HID + rc] =
                    make_float2(acc[mt][nt][2], acc[mt][nt][3]);
            }
        }
    }
}

// =====================================================================
// Edge message + scatter: 128 threads, ECHUNK=16, 16 blocks/SM.
// =====================================================================
#define ECHUNK 16
#define ETHR 128

__global__ __launch_bounds__(ETHR) void edge_kernel(int slot) {
    __shared__ __align__(16) __half sYh[COL_ROOT];   // 10560 B
    __shared__ float sh[ECHUNK * EH];                // 2048 B
    __shared__ int   sdst[ECHUNK];
    int n = blockIdx.x;
    int t = threadIdx.x;
    int beg = g_csr_off[n];
    int end = g_csr_off[n + 1];
    if (beg == end) return;

    const __half* src0 = g_Yh + (size_t)n * COL_ROOT;
    for (int i = t; i < COL_ROOT / 8; i += ETHR) {
        uint32_t dst = (uint32_t)__cvta_generic_to_shared(&sYh[i * 8]);
        asm volatile("cp.async.cg.shared.global [%0], [%1], 16;"
                     :: "r"(dst), "l"(src0 + i * 8));
    }
    asm volatile("cp.async.commit_group;");

    bool first = true;
    for (int cb = beg; cb < end; cb += ECHUNK) {
        int m = min(end - cb, ECHUNK);
        for (int i = t; i < m * EH; i += ETHR) {
            int j = i >> 5, k = i & 31;
            int e = g_csr_edge[cb + j];
            sh[i] = g_h[slot][e * EH + k];
        }
        if (t < m) sdst[t] = g_dst[g_csr_edge[cb + t]];
        if (first) {
            asm volatile("cp.async.wait_group 0;");
            first = false;
        }
        __syncthreads();

        for (int idx = t; idx < m * 40; idx += ETHR) {
            int j = idx / 40, c = (idx - j * 40) * 4;
            const float* hj = &sh[j * EH];
            float4 msg;
            {
                uint2 v = *(const uint2*)&sYh[COL_B2 + c];
                float2 a = __half22float2(((const __half2*)&v)[0]);
                float2 b = __half22float2(((const __half2*)&v)[1]);
                msg = make_float4(a.x, a.y, b.x, b.y);
            }
            #pragma unroll
            for (int k = 0; k < EH; k++) {
                float hk = hj[k];
                uint2 v = *(const uint2*)&sYh[k * HID + c];
                float2 a = __half22float2(((const __half2*)&v)[0]);
                float2 b = __half22float2(((const __half2*)&v)[1]);
                msg.x += hk * a.x;
                msg.y += hk * a.y;
                msg.z += hk * b.x;
                msg.w += hk * b.y;
            }
            atomicAdd((float4*)&g_accum[sdst[j] * HID + c], msg);
        }
        __syncthreads();
    }
}

// =====================================================================
// Finalize: v = accum/max(cnt,1) + root(fp32) + bias; re-zero accum.
// =====================================================================
__global__ void final_kernel(const float* __restrict__ bias, int outsel,
                             float* __restrict__ dout, int relu) {
    int idx = blockIdx.x * blockDim.x + threadIdx.x;
    if (idx >= N_NODES * HID) return;
    int n = idx / HID, o = idx % HID;
    float inv = 1.0f / fmaxf((float)g_cnt[n], 1.0f);
    float v = g_accum[idx] * inv + g_Yroot[idx] + bias[o];
    if (relu) v = fmaxf(v, 0.0f);
    g_accum[idx] = 0.0f;
    if (outsel == 2) {
        dout[idx] = v;
    } else {
        g_x[outsel][n * HID + kp16(o)] = __float2half_rn(v);
    }
}

// =====================================================================
// launch — prep runs on a side stream concurrently with params.
// Stream/events are created ONCE on the first (uncaptured) call;
// subsequent captured calls only record/wait (graph-capturable).
// =====================================================================
extern "C" void kernel_launch(void* const* d_in, const int* in_sizes, int n_in,
                              void* d_out, int out_size) {
    const float* x       = (const float*)d_in[0];
    const float* ea      = (const float*)d_in[1];
    const float* w1_a    = (const float*)d_in[2];
    const float* b1_a    = (const float*)d_in[3];
    const float* w2_a    = (const float*)d_in[4];
    const float* b2_a    = (const float*)d_in[5];
    const float* root_a  = (const float*)d_in[6];
    const float* bias_a  = (const float*)d_in[7];
    const float* w1_b    = (const float*)d_in[8];
    const float* b1_b    = (const float*)d_in[9];
    const float* w2_b    = (const float*)d_in[10];
    const float* b2_b    = (const float*)d_in[11];
    const float* root_b  = (const float*)d_in[12];
    const float* bias_b  = (const float*)d_in[13];
    const void*  eidx    = d_in[14];
    float* out = (float*)d_out;

    static cudaStream_t s2 = nullptr;
    static cudaEvent_t  eFork = nullptr, eJoin = nullptr;
    if (s2 == nullptr) {
        cudaFuncSetAttribute(gemm_kernel,
                             cudaFuncAttributeMaxDynamicSharedMemorySize, GEMM_SMEM);
        cudaStreamCreateWithFlags(&s2, cudaStreamNonBlocking);
        cudaEventCreateWithFlags(&eFork, cudaEventDisableTiming);
        cudaEventCreateWithFlags(&eJoin, cudaEventDisableTiming);
    }

    // fork: prep on s2, params on the launch stream, join before layer 0
    cudaEventRecord(eFork, 0);
    cudaStreamWaitEvent(s2, eFork, 0);
    prep_kernel<<<1, 1024, 0, s2>>>(eidx);
    cudaEventRecord(eJoin, s2);

    params_kernel<<<W2T_BLOCKS + 2 * BR_BLOCKS + 2 * H_BLOCKS + Z_BLOCKS + XC_BLOCKS, 256>>>(
        w2_a, w2_b, b2_a, root_a, b2_b, root_b, ea, w1_a, b1_a, w1_b, b1_b, x);

    cudaStreamWaitEvent(0, eJoin, 0);

    dim3 gemm_grid(NROWS_PAD / BN, N_NODES / BM);   // (43, 16)
    int fb = (N_NODES * HID + 255) / 256;

    // layer 0 (params a), relu — converted input lives in g_x[1]
    gemm_kernel<<<gemm_grid, 256, GEMM_SMEM>>>(1, 0);
    edge_kernel<<<N_NODES, ETHR>>>(0);
    final_kernel<<<fb, 256>>>(bias_a, 0, out, 1);

    // layer 1 (params b), relu
    gemm_kernel<<<gemm_grid, 256, GEMM_SMEM>>>(0, 1);
    edge_kernel<<<N_NODES, ETHR>>>(1);
    final_kernel<<<fb, 256>>>(bias_b, 1, out, 1);

    // layer 2 (params b), no relu -> d_out
    gemm_kernel<<<gemm_grid, 256, GEMM_SMEM>>>(1, 1);
    edge_kernel<<<N_NODES, ETHR>>>(1);
    final_kernel<<<fb, 256>>>(bias_b, 2, out, 0);
}